// round 17
// baseline (speedup 1.0000x reference)
#include <cuda_runtime.h>
#include <cuda_bf16.h>
#include <math_constants.h>
#include <cstdint>

// Problem dims (fixed)
#define BB 2
#define SS 2048
#define DD 768
#define HH 12
#define DH 64
#define BH (BB*HH)          // 24
#define ROWS_TOTAL (BB*HH*SS) // 49152

typedef unsigned long long u64;

// Scratch (device globals: sanctioned scratch mechanism)
__device__ __nv_bfloat16 g_hh[BB*SS*DD];     // hidden split-hi
__device__ __nv_bfloat16 g_hl[BB*SS*DD];     // hidden split-lo
__device__ __nv_bfloat16 g_wh[3*DD*DD];      // Wq|Wk|Wv split-hi
__device__ __nv_bfloat16 g_wl[3*DD*DD];      // Wq|Wk|Wv split-lo
__device__ __nv_bfloat16 g_qh[BB*HH*SS*DH];  // Q*0.125 split-hi
__device__ __nv_bfloat16 g_ql[BB*HH*SS*DH];  // Q*0.125 split-lo
__device__ __nv_bfloat16 g_kh[BB*HH*SS*DH];
__device__ __nv_bfloat16 g_kl[BB*HH*SS*DH];
__device__ __nv_bfloat16 g_vth[BB*HH*DH*SS]; // V^T [bh][d][s] split-hi
__device__ __nv_bfloat16 g_vtl[BB*HH*DH*SS]; // V^T split-lo

__device__ __forceinline__ uint32_t smem_u32(const void* p) {
    uint32_t a;
    asm("{ .reg .u64 t; cvta.to.shared.u64 t, %1; cvt.u32.u64 %0, t; }" : "=r"(a) : "l"(p));
    return a;
}
__device__ __forceinline__ void ldmx4(uint32_t* r, uint32_t addr) {
    asm volatile("ldmatrix.sync.aligned.m8n8.x4.shared.b16 {%0,%1,%2,%3}, [%4];"
        : "=r"(r[0]), "=r"(r[1]), "=r"(r[2]), "=r"(r[3]) : "r"(addr));
}
__device__ __forceinline__ void mma16816(float* c, const uint32_t* a, uint32_t b0, uint32_t b1) {
    asm volatile(
        "mma.sync.aligned.m16n8k16.row.col.f32.bf16.bf16.f32 "
        "{%0,%1,%2,%3},{%4,%5,%6,%7},{%8,%9},{%0,%1,%2,%3};"
        : "+f"(c[0]), "+f"(c[1]), "+f"(c[2]), "+f"(c[3])
        : "r"(a[0]), "r"(a[1]), "r"(a[2]), "r"(a[3]), "r"(b0), "r"(b1));
}
__device__ __forceinline__ uint32_t pack_bf2(__nv_bfloat16 a, __nv_bfloat16 b) {
    return (uint32_t)__bfloat16_as_ushort(a) | ((uint32_t)__bfloat16_as_ushort(b) << 16);
}
__device__ __forceinline__ uint32_t swz(uint32_t off) {
    return off ^ ((off >> 3) & 0x70);
}
__device__ __forceinline__ void cp16(uint32_t smem_addr, const void* gptr) {
    asm volatile("cp.async.cg.shared.global [%0], [%1], 16;"
                 :: "r"(smem_addr), "l"(gptr) : "memory");
}
#define CP_COMMIT() asm volatile("cp.async.commit_group;" ::: "memory")

// ---------------------------------------------------------------------------
// K0: split hid and W into bf16 hi/lo pairs.
// ---------------------------------------------------------------------------
__global__ __launch_bounds__(256) void split_kernel(
    const float* __restrict__ hid,
    const float* __restrict__ Wq, const float* __restrict__ Wk,
    const float* __restrict__ Wv)
{
    int i = blockIdx.x * 256 + threadIdx.x;
    if (i < BB*SS*DD) {
        float x = hid[i];
        __nv_bfloat16 h = __float2bfloat16(x);
        g_hh[i] = h;
        g_hl[i] = __float2bfloat16(x - __bfloat162float(h));
    }
    if (i < DD*DD) {
        float x = Wq[i];
        __nv_bfloat16 h = __float2bfloat16(x);
        g_wh[i] = h;
        g_wl[i] = __float2bfloat16(x - __bfloat162float(h));

        x = Wk[i];
        h = __float2bfloat16(x);
        g_wh[DD*DD + i] = h;
        g_wl[DD*DD + i] = __float2bfloat16(x - __bfloat162float(h));

        x = Wv[i];
        h = __float2bfloat16(x);
        g_wh[2*DD*DD + i] = h;
        g_wl[2*DD*DD + i] = __float2bfloat16(x - __bfloat162float(h));
    }
}

// ---------------------------------------------------------------------------
// K1 (mma.sync HMMA 3-split, cp.async double-buffered): QKV projection.
// ---------------------------------------------------------------------------
#define QKV_BUF  65536
#define QKV_SMEM (2*QKV_BUF)

__global__ __launch_bounds__(256) void qkv_mma_kernel(
    const float* __restrict__ bq, const float* __restrict__ bk,
    const float* __restrict__ bv)
{
    extern __shared__ __align__(1024) char smem[];
    const int tid = threadIdx.x;
    const int z = blockIdx.z;
    const int m0 = blockIdx.y * 128;
    const int n0 = blockIdx.x * 128;
    const uint32_t sb = smem_u32(smem);

    const __nv_bfloat16* Wh = g_wh + (size_t)z * DD * DD;
    const __nv_bfloat16* Wl = g_wl + (size_t)z * DD * DD;
    const float* bias = (z == 0) ? bq : (z == 1) ? bk : bv;

    const int wid = tid >> 5, lane = tid & 31;
    const int wm = wid & 3, wn = wid >> 2;
    const int mw0 = wm * 32;
    const int nw0 = wn * 64;
    const int lrow = lane & 15;
    const int lkh  = (lane >> 4) * 16;

    float acc[2][8][4];
#pragma unroll
    for (int i = 0; i < 2; i++)
#pragma unroll
        for (int j = 0; j < 8; j++)
#pragma unroll
            for (int q = 0; q < 4; q++) acc[i][j][q] = 0.f;

    auto issue_chunk = [&](int kc, uint32_t buf) {
        for (int i = tid; i < 1024; i += 256) {
            int row = i >> 3, u = i & 7;
            uint32_t sw = swz((uint32_t)(row*128 + u*16));
            size_t ga = (size_t)(m0 + row)*DD + kc + u*8;
            cp16(buf + sw,         g_hh + ga);
            cp16(buf + 16384 + sw, g_hl + ga);
            size_t gb = (size_t)(n0 + row)*DD + kc + u*8;
            cp16(buf + 32768 + sw, Wh + gb);
            cp16(buf + 49152 + sw, Wl + gb);
        }
    };

    issue_chunk(0, sb);
    CP_COMMIT();

    for (int c = 0; c < 12; c++) {
        if (c + 1 < 12) {
            issue_chunk((c + 1) * 64, sb + (uint32_t)((c + 1) & 1) * QKV_BUF);
            CP_COMMIT();
            asm volatile("cp.async.wait_group 1;" ::: "memory");
        } else {
            asm volatile("cp.async.wait_group 0;" ::: "memory");
        }
        __syncthreads();

        const uint32_t buf = sb + (uint32_t)(c & 1) * QKV_BUF;
#pragma unroll
        for (int ks = 0; ks < 4; ks++) {
            const uint32_t colb = (uint32_t)(ks*32 + lkh);
            uint32_t afh[2][4], afl[2][4];
#pragma unroll
            for (int mi = 0; mi < 2; mi++) {
                uint32_t sw = swz((uint32_t)(mw0 + mi*16 + lrow) * 128 + colb);
                ldmx4(afh[mi], buf + sw);
                ldmx4(afl[mi], buf + 16384 + sw);
            }
            uint32_t bfh[4][4], bfl[4][4];
#pragma unroll
            for (int nj = 0; nj < 4; nj++) {
                uint32_t sw = swz((uint32_t)(nw0 + nj*16 + lrow) * 128 + colb);
                ldmx4(bfh[nj], buf + 32768 + sw);
                ldmx4(bfl[nj], buf + 49152 + sw);
            }
#pragma unroll
            for (int mi = 0; mi < 2; mi++)
#pragma unroll
                for (int nj = 0; nj < 4; nj++) {
                    mma16816(acc[mi][nj*2+0], afh[mi], bfh[nj][0], bfh[nj][2]);
                    mma16816(acc[mi][nj*2+1], afh[mi], bfh[nj][1], bfh[nj][3]);
                    mma16816(acc[mi][nj*2+0], afh[mi], bfl[nj][0], bfl[nj][2]);
                    mma16816(acc[mi][nj*2+1], afh[mi], bfl[nj][1], bfl[nj][3]);
                    mma16816(acc[mi][nj*2+0], afl[mi], bfh[nj][0], bfh[nj][2]);
                    mma16816(acc[mi][nj*2+1], afl[mi], bfh[nj][1], bfh[nj][3]);
                }
        }
        __syncthreads();
    }

    const float sc = (z == 0) ? 0.125f : 1.0f;
    __nv_bfloat16* oh = (z == 0) ? g_qh : g_kh;
    __nv_bfloat16* ol = (z == 0) ? g_ql : g_kl;

#pragma unroll
    for (int mi = 0; mi < 2; mi++) {
#pragma unroll
        for (int half = 0; half < 2; half++) {
            int m = m0 + mw0 + mi*16 + (lane >> 2) + half*8;
            int b = m >> 11, s = m & 2047;
#pragma unroll
            for (int nj = 0; nj < 8; nj++) {
                int n = n0 + nw0 + nj*8 + (lane & 3)*2;
                float x0 = acc[mi][nj][half*2+0] + bias[n];
                float x1 = acc[mi][nj][half*2+1] + bias[n+1];
                if (z == 2) {
                    int h = n >> 6, d = n & 63;
                    __nv_bfloat16 h0 = __float2bfloat16(x0);
                    __nv_bfloat16 h1 = __float2bfloat16(x1);
                    size_t i0 = ((size_t)((b*HH + h)*DH + d))*SS + s;
                    size_t i1 = ((size_t)((b*HH + h)*DH + d + 1))*SS + s;
                    g_vth[i0] = h0;
                    g_vtl[i0] = __float2bfloat16(x0 - __bfloat162float(h0));
                    g_vth[i1] = h1;
                    g_vtl[i1] = __float2bfloat16(x1 - __bfloat162float(h1));
                } else {
                    x0 *= sc; x1 *= sc;
                    int h = n >> 6, d = n & 63;
                    __nv_bfloat16 h0 = __float2bfloat16(x0);
                    __nv_bfloat16 h1 = __float2bfloat16(x1);
                    size_t idx = (((size_t)(b*HH + h)*SS + s) << 6) + d;
                    *(uint32_t*)(oh + idx) = pack_bf2(h0, h1);
                    *(uint32_t*)(ol + idx) = pack_bf2(
                        __float2bfloat16(x0 - __bfloat162float(h0)),
                        __float2bfloat16(x1 - __bfloat162float(h1)));
                }
            }
        }
    }
}

// ---------------------------------------------------------------------------
// K2 (fused flash attention, cp.async pipelined, 64-col chunks, 3 CTAs/SM):
// res read via __ldcs, scores write via __stcs (streaming, L2-friendly).
// mask staged ONCE (8 KB).
// smem: Kbuf0 16K | Kbuf1 16K (Q staged first) | VH 8K | VL 8K | mask 8K
// ---------------------------------------------------------------------------
#define FA_OF_V  32768
#define FA_OF_MK 49152
#define FA_SMEM  (49152 + 8192)

__global__ __launch_bounds__(128, 3) void fused_attn_kernel(
    const float* __restrict__ res, const float* __restrict__ mask,
    float* __restrict__ out_scores, float* __restrict__ ctx)
{
    extern __shared__ __align__(1024) char smem[];
    const int tid = threadIdx.x;
    const int bh = blockIdx.y;
    const int b = bh / HH, h = bh % HH;
    const int m0 = blockIdx.x * 64;
    const uint32_t sb = smem_u32(smem);

    const int wid = tid >> 5, lane = tid & 31;
    const int lrow = lane & 15;
    const int lkh  = (lane >> 4) * 16;
    const int cbase = (lane & 3) * 2;
    const int wrow = wid * 16;

    // --- Stage mask (full 8 KB, once) via cp.async ---
    {
        const float* mask_g = mask + (size_t)b*SS;
        for (int i = tid; i < 512; i += 128)
            cp16(sb + FA_OF_MK + (uint32_t)i*16, mask_g + i*4);
    }
    CP_COMMIT();

    // --- Stage Q hi/lo (64x64) into Kbuf1; load resident A-frags ---
    {
        const uint4* sqh = (const uint4*)(g_qh + (size_t)(bh*SS + m0)*DH);
        const uint4* sql = (const uint4*)(g_ql + (size_t)(bh*SS + m0)*DH);
        for (int i = tid; i < 512; i += 128) {
            uint32_t sw = swz((uint32_t)i * 16);
            *(uint4*)(smem + 16384 + sw) = sqh[i];
            *(uint4*)(smem + 16384 + 8192 + sw) = sql[i];
        }
    }
    __syncthreads();

    uint32_t qa_h[4][4], qa_l[4][4];
#pragma unroll
    for (int t = 0; t < 4; t++) {
        uint32_t sw = swz((uint32_t)(wrow + lrow) * 128 + t*32 + lkh);
        ldmx4(qa_h[t], sb + 16384 + sw);
        ldmx4(qa_l[t], sb + 16384 + 8192 + sw);
    }
    __syncthreads();   // Q consumed; Kbuf1 free

    const __nv_bfloat16* vth = g_vth + (size_t)(bh*DH)*SS;
    const __nv_bfloat16* vtl = g_vtl + (size_t)(bh*DH)*SS;
    const __nv_bfloat16* kph = g_kh + (size_t)(bh*SS)*DH;
    const __nv_bfloat16* kpl = g_kl + (size_t)(bh*SS)*DH;

    // --- prefetch chunk 0: K (64x64 hi/lo) -> buf0 ---
    {
        const uint4* skh = (const uint4*)kph;
        const uint4* skl = (const uint4*)kpl;
        for (int i = tid; i < 512; i += 128) {
            uint32_t sw = swz((uint32_t)i * 16);
            cp16(sb + sw, skh + i);
            cp16(sb + 8192 + sw, skl + i);
        }
    }
    CP_COMMIT();

    // --- running stats + O accumulator ---
    float mrun0 = -CUDART_INF_F, mrun1 = -CUDART_INF_F;
    float lrun0 = 0.f, lrun1 = 0.f;
    float O[8][4];
#pragma unroll
    for (int j = 0; j < 8; j++)
#pragma unroll
        for (int q = 0; q < 4; q++) O[j][q] = 0.f;

    const int r0 = wrow + (lane >> 2);
    const int r1 = r0 + 8;
    const float* Rrow0 = res + (size_t)bh*SS*SS + (size_t)(m0 + r0)*SS;
    const float* Rrow1 = res + (size_t)bh*SS*SS + (size_t)(m0 + r1)*SS;
    float* Srow0 = out_scores + (size_t)bh*SS*SS + (size_t)(m0 + r0)*SS;
    float* Srow1 = out_scores + (size_t)bh*SS*SS + (size_t)(m0 + r1)*SS;
    const float* masksm = (const float*)(smem + FA_OF_MK);

    for (int it = 0; it < 32; it++) {
        const int cur = it & 1;
        const int n0 = it * 64;

        // ---- issue V(it): [d 0..63][s 64] hi/lo ----
        for (int i = tid; i < 512; i += 128) {
            int d = i >> 3, u = i & 7;
            size_t g = (size_t)d * SS + n0 + u*8;
            uint32_t sw = swz((uint32_t)(d*128 + u*16));
            cp16(sb + FA_OF_V + sw, vth + g);
            cp16(sb + FA_OF_V + 8192 + sw, vtl + g);
        }
        CP_COMMIT();

        // ---- issue K(it+1) ----
        if (it + 1 < 32) {
            const int nn = n0 + 64;
            const uint4* skh = (const uint4*)(kph + (size_t)nn*DH);
            const uint4* skl = (const uint4*)(kpl + (size_t)nn*DH);
            const uint32_t kb = (uint32_t)(1 - cur) * 16384;
            for (int i = tid; i < 512; i += 128) {
                uint32_t sw = swz((uint32_t)i * 16);
                cp16(sb + kb + sw, skh + i);
                cp16(sb + kb + 8192 + sw, skl + i);
            }
            CP_COMMIT();
            asm volatile("cp.async.wait_group 1;" ::: "memory");
        } else {
            asm volatile("cp.async.wait_group 0;" ::: "memory");
        }
        __syncthreads();

        const uint32_t kb = (uint32_t)cur * 16384;

        // ---- S = Qs K^T (3-split), 64 cols ----
        float sfr[8][4];
#pragma unroll
        for (int j = 0; j < 8; j++)
#pragma unroll
            for (int q = 0; q < 4; q++) sfr[j][q] = 0.f;

#pragma unroll
        for (int kt = 0; kt < 4; kt++) {
            const uint32_t colb = (uint32_t)(kt*32 + lkh);
#pragma unroll
            for (int j = 0; j < 4; j++) {
                uint32_t sw = swz((uint32_t)(j*16 + lrow) * 128 + colb);
                uint32_t bb[4];
                ldmx4(bb, sb + kb + sw);
                mma16816(sfr[2*j+0], qa_h[kt], bb[0], bb[2]);
                mma16816(sfr[2*j+1], qa_h[kt], bb[1], bb[3]);
                mma16816(sfr[2*j+0], qa_l[kt], bb[0], bb[2]);
                mma16816(sfr[2*j+1], qa_l[kt], bb[1], bb[3]);
                ldmx4(bb, sb + kb + 8192 + sw);
                mma16816(sfr[2*j+0], qa_h[kt], bb[0], bb[2]);
                mma16816(sfr[2*j+1], qa_h[kt], bb[1], bb[3]);
            }
        }

        // ---- +res (streaming), write scores (streaming), +mask, tile max ----
        float tmax0 = -CUDART_INF_F, tmax1 = -CUDART_INF_F;
#pragma unroll
        for (int j = 0; j < 8; j++) {
            int col = n0 + j*8 + cbase;
            float2 rv0 = __ldcs((const float2*)(Rrow0 + col));
            float2 rv1 = __ldcs((const float2*)(Rrow1 + col));
            float s00 = sfr[j][0] + rv0.x, s01 = sfr[j][1] + rv0.y;
            float s10 = sfr[j][2] + rv1.x, s11 = sfr[j][3] + rv1.y;
            __stcs((float2*)(Srow0 + col), make_float2(s00, s01));
            __stcs((float2*)(Srow1 + col), make_float2(s10, s11));
            float mk0 = masksm[col], mk1 = masksm[col + 1];
            s00 += mk0; s01 += mk1; s10 += mk0; s11 += mk1;
            sfr[j][0] = s00; sfr[j][1] = s01; sfr[j][2] = s10; sfr[j][3] = s11;
            tmax0 = fmaxf(tmax0, fmaxf(s00, s01));
            tmax1 = fmaxf(tmax1, fmaxf(s10, s11));
        }
        tmax0 = fmaxf(tmax0, __shfl_xor_sync(0xffffffffu, tmax0, 1));
        tmax0 = fmaxf(tmax0, __shfl_xor_sync(0xffffffffu, tmax0, 2));
        tmax1 = fmaxf(tmax1, __shfl_xor_sync(0xffffffffu, tmax1, 1));
        tmax1 = fmaxf(tmax1, __shfl_xor_sync(0xffffffffu, tmax1, 2));

        // ---- online rescale ----
        float mnew0 = fmaxf(mrun0, tmax0);
        float mnew1 = fmaxf(mrun1, tmax1);
        float sc0 = __expf(mrun0 - mnew0);
        float sc1 = __expf(mrun1 - mnew1);
        mrun0 = mnew0; mrun1 = mnew1;
        lrun0 *= sc0; lrun1 *= sc1;
#pragma unroll
        for (int j = 0; j < 8; j++) {
            O[j][0] *= sc0; O[j][1] *= sc0;
            O[j][2] *= sc1; O[j][3] *= sc1;
        }

        // ---- exp + pack P into A-frags (hi/lo) ----
        uint32_t pah[4][4], pal[4][4];
#pragma unroll
        for (int j = 0; j < 8; j++) {
            float e0 = __expf(sfr[j][0] - mnew0);
            float e1 = __expf(sfr[j][1] - mnew0);
            float e2 = __expf(sfr[j][2] - mnew1);
            float e3 = __expf(sfr[j][3] - mnew1);
            lrun0 += e0 + e1;
            lrun1 += e2 + e3;
            __nv_bfloat16 h0 = __float2bfloat16(e0), h1 = __float2bfloat16(e1);
            __nv_bfloat16 h2 = __float2bfloat16(e2), h3 = __float2bfloat16(e3);
            int t = j >> 1, odd = j & 1;
            pah[t][odd*2+0] = pack_bf2(h0, h1);
            pah[t][odd*2+1] = pack_bf2(h2, h3);
            pal[t][odd*2+0] = pack_bf2(__float2bfloat16(e0 - __bfloat162float(h0)),
                                       __float2bfloat16(e1 - __bfloat162float(h1)));
            pal[t][odd*2+1] = pack_bf2(__float2bfloat16(e2 - __bfloat162float(h2)),
                                       __float2bfloat16(e3 - __bfloat162float(h3)));
        }

        // ---- O += P V (3-split) ----
#pragma unroll
        for (int ks = 0; ks < 4; ks++) {
            const uint32_t colb = (uint32_t)(ks*32 + lkh);
#pragma unroll
            for (int nj = 0; nj < 4; nj++) {
                uint32_t sw = swz((uint32_t)(nj*16 + lrow) * 128 + colb);
                uint32_t vv[4];
                ldmx4(vv, sb + FA_OF_V + sw);
                mma16816(O[2*nj+0], pah[ks], vv[0], vv[2]);
                mma16816(O[2*nj+1], pah[ks], vv[1], vv[3]);
                mma16816(O[2*nj+0], pal[ks], vv[0], vv[2]);
                mma16816(O[2*nj+1], pal[ks], vv[1], vv[3]);
                ldmx4(vv, sb + FA_OF_V + 8192 + sw);
                mma16816(O[2*nj+0], pah[ks], vv[0], vv[2]);
                mma16816(O[2*nj+1], pah[ks], vv[1], vv[3]);
            }
        }
        __syncthreads();
    }

    // ---- finalize ----
    lrun0 += __shfl_xor_sync(0xffffffffu, lrun0, 1);
    lrun0 += __shfl_xor_sync(0xffffffffu, lrun0, 2);
    lrun1 += __shfl_xor_sync(0xffffffffu, lrun1, 1);
    lrun1 += __shfl_xor_sync(0xffffffffu, lrun1, 2);
    float rl0 = 1.0f / lrun0;
    float rl1 = 1.0f / lrun1;

    float* c0 = ctx + ((size_t)b*SS + m0 + r0)*DD + h*DH + cbase;
    float* c1 = ctx + ((size_t)b*SS + m0 + r1)*DD + h*DH + cbase;
#pragma unroll
    for (int nj = 0; nj < 8; nj++) {
        *(float2*)(c0 + nj*8) = make_float2(O[nj][0]*rl0, O[nj][1]*rl0);
        *(float2*)(c1 + nj*8) = make_float2(O[nj][2]*rl1, O[nj][3]*rl1);
    }
}

// ---------------------------------------------------------------------------
extern "C" void kernel_launch(void* const* d_in, const int* in_sizes, int n_in,
                              void* d_out, int out_size)
{
    const float* hid  = (const float*)d_in[0];
    const float* mask = (const float*)d_in[1];
    const float* res  = (const float*)d_in[2];
    const float* Wq = (const float*)d_in[3];
    const float* bq = (const float*)d_in[4];
    const float* Wk = (const float*)d_in[5];
    const float* bk = (const float*)d_in[6];
    const float* Wv = (const float*)d_in[7];
    const float* bv = (const float*)d_in[8];

    float* out_ctx    = (float*)d_out;
    float* out_scores = (float*)d_out + (size_t)BB*SS*DD;

    cudaFuncSetAttribute(qkv_mma_kernel,
                         cudaFuncAttributeMaxDynamicSharedMemorySize, QKV_SMEM);
    cudaFuncSetAttribute(fused_attn_kernel,
                         cudaFuncAttributeMaxDynamicSharedMemorySize, FA_SMEM);

    split_kernel<<<(BB*SS*DD + 255)/256, 256>>>(hid, Wq, Wk, Wv);
    qkv_mma_kernel<<<dim3(DD/128, (BB*SS)/128, 3), 256, QKV_SMEM>>>(bq, bk, bv);
    fused_attn_kernel<<<dim3(SS/64, BH), 128, FA_SMEM>>>(res, mask, out_scores, out_ctx);
}